// round 4
// baseline (speedup 1.0000x reference)
#include <cuda_runtime.h>

#define NN 50000
#define EE 800000
#define ET 850000   // EE + NN self-loops
#define SB 512      // scan block size
#define NB ((NN + SB - 1) / SB)   // 98 scan blocks

// ---------------- scratch (device globals; no runtime allocation) ----------
__device__ int   g_deg[NN];
__device__ int   g_cur[NN];
__device__ int   g_off[NN + 1];
__device__ float g_dis[NN];
__device__ int   g_rowE[EE];
__device__ int   g_colE[EE];
__device__ int   g_part[NB];
__device__ int   g_pscan[NB];
__device__ int   g_src[ET];
__device__ float g_w[ET];
__device__ float g_bufA[(size_t)NN * 128];
__device__ float g_bufB[(size_t)NN * 128];

// Compile-time buffer selector (no host-side symbol lookup).
enum Which { A_, B_, X_ };
template <Which W>
__device__ __forceinline__ const float* inbuf(const float* ext) {
    if constexpr (W == A_) return g_bufA;
    else if constexpr (W == B_) return g_bufB;
    else return ext;
}
template <Which W>
__device__ __forceinline__ float* outbuf(float* ext) {
    if constexpr (W == A_) return g_bufA;
    else if constexpr (W == B_) return g_bufB;
    else return ext;
}

// ---------------- graph prep ------------------------------------------------
__global__ void k_zero() {
    int i = blockIdx.x * blockDim.x + threadIdx.x;
    if (i < NN) { g_deg[i] = 0; g_cur[i] = 0; }
}

// edge_index is int32 (JAX x64 disabled)
__global__ void k_count(const int* __restrict__ ei) {
    int e = blockIdx.x * blockDim.x + threadIdx.x;
    if (e >= EE) return;
    int r = ei[e];
    int c = ei[EE + e];
    if ((unsigned)r >= NN) r = 0;   // never trap on bad data (no-op when valid)
    if ((unsigned)c >= NN) c = 0;
    g_rowE[e] = r;
    g_colE[e] = c;
    atomicAdd(&g_deg[c], 1);
}

// phase 1: per-block sums of (deg[i]+1)
__global__ __launch_bounds__(SB) void k_scan1() {
    __shared__ int s[SB];
    int t = threadIdx.x;
    int i = blockIdx.x * SB + t;
    s[t] = (i < NN) ? (g_deg[i] + 1) : 0;
    __syncthreads();
#pragma unroll
    for (int o = SB / 2; o > 0; o >>= 1) {
        if (t < o) s[t] += s[t + o];
        __syncthreads();
    }
    if (t == 0) g_part[blockIdx.x] = s[0];
}

// phase 2: exclusive scan of the NB partials (single block of 128)
__global__ __launch_bounds__(128) void k_scan2() {
    __shared__ int s[128];
    int t = threadIdx.x;
    int v = (t < NB) ? g_part[t] : 0;
    s[t] = v;
    __syncthreads();
#pragma unroll
    for (int o = 1; o < 128; o <<= 1) {
        int u = (t >= o) ? s[t - o] : 0;
        __syncthreads();
        s[t] += u;
        __syncthreads();
    }
    if (t < NB) g_pscan[t] = s[t] - v;
    if (t == 0) g_off[NN] = ET;   // total is a compile-time constant
}

// phase 3: block-local exclusive scan + base, write g_off and g_dis
__global__ __launch_bounds__(SB) void k_scan3() {
    __shared__ int s[SB];
    int t = threadIdx.x;
    int i = blockIdx.x * SB + t;
    int d = (i < NN) ? g_deg[i] : 0;
    int v = (i < NN) ? (d + 1) : 0;
    s[t] = v;
    __syncthreads();
#pragma unroll
    for (int o = 1; o < SB; o <<= 1) {
        int u = (t >= o) ? s[t - o] : 0;
        __syncthreads();
        s[t] += u;
        __syncthreads();
    }
    if (i < NN) {
        g_off[i] = g_pscan[blockIdx.x] + s[t] - v;
        g_dis[i] = rsqrtf((float)(d + 1));
    }
}

// fill CSR: edges + self loops in one kernel
__global__ void k_fillself() {
    int e = blockIdx.x * blockDim.x + threadIdx.x;
    if (e < EE) {
        int r = g_rowE[e], c = g_colE[e];
        int p = atomicAdd(&g_cur[c], 1);
        int idx = g_off[c] + p;
        g_src[idx] = r;
        g_w[idx] = g_dis[r] * g_dis[c];
    } else if (e < EE + NN) {
        int n = e - EE;
        int idx = g_off[n + 1] - 1;   // last slot of each segment
        g_src[idx] = n;
        float d = g_dis[n];
        g_w[idx] = d * d;
    }
}

// ---------------- aggregation: out[n] = (bias) + sum_e w_e * h[src_e] ------
// One warp per node. Edge (idx, w) pairs prefetched 32-at-a-time with
// coalesced loads and broadcast via shfl, so feature-row LDGs have no
// scalar load in their dependency chain.
template <int F, bool BIAS, Which SRC, Which DST>
__global__ __launch_bounds__(256) void k_agg(const float* __restrict__ ext_in,
                                             const float* __restrict__ b,
                                             float* __restrict__ ext_out) {
    const float* __restrict__ h = inbuf<SRC>(ext_in);
    float* __restrict__ out = outbuf<DST>(ext_out);
    constexpr int NACC = (F + 31) / 32;
    int warp = (blockIdx.x * blockDim.x + threadIdx.x) >> 5;
    int lane = threadIdx.x & 31;
    if (warp >= NN) return;
    int n = warp;
    int s = g_off[n], e = g_off[n + 1];
    float acc[NACC];
#pragma unroll
    for (int j = 0; j < NACC; j++) acc[j] = 0.f;

    for (int base = s; base < e; base += 32) {
        int cnt = e - base; if (cnt > 32) cnt = 32;
        int   my_idx = 0;
        float my_w   = 0.f;
        if (lane < cnt) {
            my_idx = g_src[base + lane];
            my_w   = g_w[base + lane];
        }
        for (int t = 0; t < cnt; t++) {
            int   src = __shfl_sync(0xffffffffu, my_idx, t);
            float w   = __shfl_sync(0xffffffffu, my_w, t);
            const float* hp = h + (size_t)src * F;
#pragma unroll
            for (int j = 0; j < NACC; j++) {
                int f = lane + 32 * j;
                if (f < F) acc[j] += w * __ldg(hp + f);
            }
        }
    }
    float* op = out + (size_t)n * F;
#pragma unroll
    for (int j = 0; j < NACC; j++) {
        int f = lane + 32 * j;
        if (f < F) op[f] = acc[j] + (BIAS ? __ldg(b + f) : 0.f);
    }
}

// ---------------- GEMM: out[n][o] = (bias[o]) + sum_k x[n][k]*W[k][o] ------
template <int IN, int OUT, bool BIAS, bool RELU, Which SRC, Which DST>
__global__ void k_gemm(const float* __restrict__ ext_in,
                       const float* __restrict__ W,
                       const float* __restrict__ b,
                       float* __restrict__ ext_out) {
    const float* __restrict__ x = inbuf<SRC>(ext_in);
    float* __restrict__ out = outbuf<DST>(ext_out);
    constexpr int YB = 256 / OUT;   // rows of threads per block
    constexpr int NPT = 8;          // nodes per thread (register blocking)
    __shared__ float Ws[IN * OUT];
    for (int i = threadIdx.x; i < IN * OUT; i += blockDim.x) Ws[i] = W[i];
    __syncthreads();
    int o = threadIdx.x % OUT;
    int yy = threadIdx.x / OUT;
    int nodeBase = (blockIdx.x * YB + yy) * NPT;
    if (nodeBase >= NN) return;
    float acc[NPT];
    float bias = BIAS ? b[o] : 0.f;
#pragma unroll
    for (int j = 0; j < NPT; j++) acc[j] = 0.f;
    const float* xr = x + (size_t)nodeBase * IN;
    if (nodeBase + NPT <= NN) {
#pragma unroll
        for (int k = 0; k < IN; k++) {
            float w = Ws[k * OUT + o];
#pragma unroll
            for (int j = 0; j < NPT; j++) acc[j] += xr[(size_t)j * IN + k] * w;
        }
#pragma unroll
        for (int j = 0; j < NPT; j++) {
            float v = acc[j] + bias;
            out[(size_t)(nodeBase + j) * OUT + o] = RELU ? fmaxf(v, 0.f) : v;
        }
    } else {
        for (int k = 0; k < IN; k++) {
            float w = Ws[k * OUT + o];
#pragma unroll
            for (int j = 0; j < NPT; j++)
                if (nodeBase + j < NN) acc[j] += xr[(size_t)j * IN + k] * w;
        }
#pragma unroll
        for (int j = 0; j < NPT; j++)
            if (nodeBase + j < NN) {
                float v = acc[j] + bias;
                out[(size_t)(nodeBase + j) * OUT + o] = RELU ? fmaxf(v, 0.f) : v;
            }
    }
}

// ---------------- launch ----------------------------------------------------
static inline int ceil_div(int a, int b) { return (a + b - 1) / b; }

extern "C" void kernel_launch(void* const* d_in, const int* in_sizes, int n_in,
                              void* d_out, int out_size) {
    const float* x  = (const float*)d_in[0];
    const int*   ei = (const int*)d_in[1];   // int32 edge_index (2, E)
    const float* W1 = (const float*)d_in[2]; const float* b1 = (const float*)d_in[3];
    const float* W2 = (const float*)d_in[4]; const float* b2 = (const float*)d_in[5];
    const float* W3 = (const float*)d_in[6]; const float* b3 = (const float*)d_in[7];
    const float* W4 = (const float*)d_in[8]; const float* b4 = (const float*)d_in[9];
    float* out = (float*)d_out;

    const int TB = 256;
    const int gN  = ceil_div(NN, TB);
    const int gE  = ceil_div(EE, TB);
    const int gET = ceil_div(ET, TB);
    const int gW  = ceil_div(NN, TB / 32);   // one warp per node

    // graph prep
    k_zero<<<gN, TB>>>();
    k_count<<<gE, TB>>>(ei);
    k_scan1<<<NB, SB>>>();
    k_scan2<<<1, 128>>>();
    k_scan3<<<NB, SB>>>();
    k_fillself<<<gET, TB>>>();

    // layer 1: h1 = relu((A x) W1 + b1)   — aggregate 29 feats, then GEMM
    k_agg<29, false, X_, A_><<<gW, TB>>>(x, nullptr, nullptr);
    k_gemm<29, 96, true, true, A_, B_>
        <<<ceil_div(NN, (256/96)*8), (256/96)*96>>>(nullptr, W1, b1, nullptr);

    // layer 2: h2 = (A h1) W2 + b2       — aggregate 96 feats, then GEMM
    k_agg<96, false, B_, A_><<<gW, TB>>>(nullptr, nullptr, nullptr);
    k_gemm<96, 128, true, false, A_, B_>
        <<<ceil_div(NN, (256/128)*8), 256>>>(nullptr, W2, b2, nullptr);

    // layer 3: h3 = A (h2 W3) + b3       — GEMM first (64 < 128), agg with bias
    k_gemm<128, 64, false, false, B_, A_>
        <<<ceil_div(NN, (256/64)*8), 256>>>(nullptr, W3, nullptr, nullptr);
    k_agg<64, true, A_, B_><<<gW, TB>>>(nullptr, b3, nullptr);

    // layer 4: out = A (h3 W4) + b4      — GEMM first (32 < 64), agg with bias
    k_gemm<64, 32, false, false, B_, A_>
        <<<ceil_div(NN, (256/32)*8), 256>>>(nullptr, W4, nullptr, nullptr);
    k_agg<32, true, A_, X_><<<gW, TB>>>(nullptr, b4, out);

    (void)in_sizes; (void)n_in; (void)out_size;
}

// round 6
// speedup vs baseline: 1.4610x; 1.4610x over previous
#include <cuda_runtime.h>

#define NN 50000
#define EE 800000
#define ET 850000   // EE + NN self-loops
#define SB 512      // scan block size
#define NB ((NN + SB - 1) / SB)   // 98 scan blocks

// ---------------- scratch (device globals; no runtime allocation) ----------
__device__ int   g_deg[NN];
__device__ int   g_cur[NN];
__device__ int   g_off[NN + 1];
__device__ float g_dis[NN];
__device__ int   g_rowE[EE];
__device__ int   g_colE[EE];
__device__ int   g_part[NB];
__device__ int   g_pscan[NB];
__device__ int   g_src[ET];
__device__ float g_w[ET];
__device__ float g_bufA[(size_t)NN * 128];
__device__ float g_bufB[(size_t)NN * 128];

// Compile-time buffer selector (no host-side symbol lookup).
enum Which { A_, B_, X_ };
template <Which W>
__device__ __forceinline__ const float* inbuf(const float* ext) {
    if constexpr (W == A_) return g_bufA;
    else if constexpr (W == B_) return g_bufB;
    else return ext;
}
template <Which W>
__device__ __forceinline__ float* outbuf(float* ext) {
    if constexpr (W == A_) return g_bufA;
    else if constexpr (W == B_) return g_bufB;
    else return ext;
}

// ---------------- graph prep ------------------------------------------------
__global__ void k_zero() {
    int i = blockIdx.x * blockDim.x + threadIdx.x;
    if (i < NN) { g_deg[i] = 0; g_cur[i] = 0; }
}

// edge_index is int32 (JAX x64 disabled)
__global__ void k_count(const int* __restrict__ ei) {
    int e = blockIdx.x * blockDim.x + threadIdx.x;
    if (e >= EE) return;
    int r = ei[e];
    int c = ei[EE + e];
    if ((unsigned)r >= NN) r = 0;   // never trap on bad data (no-op when valid)
    if ((unsigned)c >= NN) c = 0;
    g_rowE[e] = r;
    g_colE[e] = c;
    atomicAdd(&g_deg[c], 1);
}

// phase 1: per-block sums of (deg[i]+1)
__global__ __launch_bounds__(SB) void k_scan1() {
    __shared__ int s[SB];
    int t = threadIdx.x;
    int i = blockIdx.x * SB + t;
    s[t] = (i < NN) ? (g_deg[i] + 1) : 0;
    __syncthreads();
#pragma unroll
    for (int o = SB / 2; o > 0; o >>= 1) {
        if (t < o) s[t] += s[t + o];
        __syncthreads();
    }
    if (t == 0) g_part[blockIdx.x] = s[0];
}

// phase 2: exclusive scan of the NB partials (single block of 128)
__global__ __launch_bounds__(128) void k_scan2() {
    __shared__ int s[128];
    int t = threadIdx.x;
    int v = (t < NB) ? g_part[t] : 0;
    s[t] = v;
    __syncthreads();
#pragma unroll
    for (int o = 1; o < 128; o <<= 1) {
        int u = (t >= o) ? s[t - o] : 0;
        __syncthreads();
        s[t] += u;
        __syncthreads();
    }
    if (t < NB) g_pscan[t] = s[t] - v;
    if (t == 0) g_off[NN] = ET;   // total is a compile-time constant
}

// phase 3: block-local exclusive scan + base, write g_off and g_dis
__global__ __launch_bounds__(SB) void k_scan3() {
    __shared__ int s[SB];
    int t = threadIdx.x;
    int i = blockIdx.x * SB + t;
    int d = (i < NN) ? g_deg[i] : 0;
    int v = (i < NN) ? (d + 1) : 0;
    s[t] = v;
    __syncthreads();
#pragma unroll
    for (int o = 1; o < SB; o <<= 1) {
        int u = (t >= o) ? s[t - o] : 0;
        __syncthreads();
        s[t] += u;
        __syncthreads();
    }
    if (i < NN) {
        g_off[i] = g_pscan[blockIdx.x] + s[t] - v;
        g_dis[i] = rsqrtf((float)(d + 1));
    }
}

// fill CSR: edges + self loops in one kernel
__global__ void k_fillself() {
    int e = blockIdx.x * blockDim.x + threadIdx.x;
    if (e < EE) {
        int r = g_rowE[e], c = g_colE[e];
        int p = atomicAdd(&g_cur[c], 1);
        int idx = g_off[c] + p;
        g_src[idx] = r;
        g_w[idx] = g_dis[r] * g_dis[c];
    } else if (e < EE + NN) {
        int n = e - EE;
        int idx = g_off[n + 1] - 1;   // last slot of each segment
        g_src[idx] = n;
        float d = g_dis[n];
        g_w[idx] = d * d;
    }
}

// ---------------- aggregation: out[n] = (bias) + sum_e w_e * h[src_e] ------
// One warp per node (R3 version — per-warp broadcast scalar loads are L1-hit
// and ptxas pipelines the feature LDGs; do NOT reintroduce shfl broadcast).
template <int F, bool BIAS, Which SRC, Which DST>
__global__ __launch_bounds__(256) void k_agg(const float* __restrict__ ext_in,
                                             const float* __restrict__ b,
                                             float* __restrict__ ext_out) {
    const float* __restrict__ h = inbuf<SRC>(ext_in);
    float* __restrict__ out = outbuf<DST>(ext_out);
    constexpr int NACC = (F + 31) / 32;
    int warp = (blockIdx.x * blockDim.x + threadIdx.x) >> 5;
    int lane = threadIdx.x & 31;
    if (warp >= NN) return;
    int n = warp;
    int s = g_off[n], e = g_off[n + 1];
    float acc[NACC];
#pragma unroll
    for (int j = 0; j < NACC; j++) acc[j] = 0.f;
    for (int i = s; i < e; i++) {
        int src = g_src[i];
        float w = g_w[i];
        const float* hp = h + (size_t)src * F;
#pragma unroll
        for (int j = 0; j < NACC; j++) {
            int f = lane + 32 * j;
            if (f < F) acc[j] += w * __ldg(hp + f);
        }
    }
    float* op = out + (size_t)n * F;
#pragma unroll
    for (int j = 0; j < NACC; j++) {
        int f = lane + 32 * j;
        if (f < F) op[f] = acc[j] + (BIAS ? b[f] : 0.f);
    }
}

// ---------------- GEMM: out[n][o] = (bias[o]) + sum_k x[n][k]*W[k][o] ------
template <int IN, int OUT, bool BIAS, bool RELU, Which SRC, Which DST>
__global__ void k_gemm(const float* __restrict__ ext_in,
                       const float* __restrict__ W,
                       const float* __restrict__ b,
                       float* __restrict__ ext_out) {
    const float* __restrict__ x = inbuf<SRC>(ext_in);
    float* __restrict__ out = outbuf<DST>(ext_out);
    constexpr int YB = 256 / OUT;       // 96->2,128->2,64->4,32->8
    constexpr int NPT = 4;              // nodes per thread (R3 known-good)
    __shared__ float Ws[IN * OUT];
    for (int i = threadIdx.x; i < IN * OUT; i += blockDim.x) Ws[i] = W[i];
    __syncthreads();
    int o = threadIdx.x % OUT;
    int yy = threadIdx.x / OUT;
    int nodeBase = (blockIdx.x * YB + yy) * NPT;
    if (nodeBase >= NN) return;
    float acc[NPT];
    float bias = BIAS ? b[o] : 0.f;
#pragma unroll
    for (int j = 0; j < NPT; j++) acc[j] = 0.f;
    const float* xr = x + (size_t)nodeBase * IN;
    if (nodeBase + NPT <= NN) {
#pragma unroll
        for (int k = 0; k < IN; k++) {
            float w = Ws[k * OUT + o];
#pragma unroll
            for (int j = 0; j < NPT; j++) acc[j] += xr[(size_t)j * IN + k] * w;
        }
#pragma unroll
        for (int j = 0; j < NPT; j++) {
            float v = acc[j] + bias;
            out[(size_t)(nodeBase + j) * OUT + o] = RELU ? fmaxf(v, 0.f) : v;
        }
    } else {
        for (int k = 0; k < IN; k++) {
            float w = Ws[k * OUT + o];
#pragma unroll
            for (int j = 0; j < NPT; j++)
                if (nodeBase + j < NN) acc[j] += xr[(size_t)j * IN + k] * w;
        }
#pragma unroll
        for (int j = 0; j < NPT; j++)
            if (nodeBase + j < NN) {
                float v = acc[j] + bias;
                out[(size_t)(nodeBase + j) * OUT + o] = RELU ? fmaxf(v, 0.f) : v;
            }
    }
}

// ---------------- launch ----------------------------------------------------
static inline int ceil_div(int a, int b) { return (a + b - 1) / b; }

extern "C" void kernel_launch(void* const* d_in, const int* in_sizes, int n_in,
                              void* d_out, int out_size) {
    const float* x  = (const float*)d_in[0];
    const int*   ei = (const int*)d_in[1];   // int32 edge_index (2, E)
    const float* W1 = (const float*)d_in[2]; const float* b1 = (const float*)d_in[3];
    const float* W2 = (const float*)d_in[4]; const float* b2 = (const float*)d_in[5];
    const float* W3 = (const float*)d_in[6]; const float* b3 = (const float*)d_in[7];
    const float* W4 = (const float*)d_in[8]; const float* b4 = (const float*)d_in[9];
    float* out = (float*)d_out;

    const int TB = 256;
    const int gN  = ceil_div(NN, TB);
    const int gE  = ceil_div(EE, TB);
    const int gET = ceil_div(ET, TB);
    const int gW  = ceil_div(NN, TB / 32);   // one warp per node

    // graph prep
    k_zero<<<gN, TB>>>();
    k_count<<<gE, TB>>>(ei);
    k_scan1<<<NB, SB>>>();
    k_scan2<<<1, 128>>>();
    k_scan3<<<NB, SB>>>();
    k_fillself<<<gET, TB>>>();

    // layer 1: h1 = relu((A x) W1 + b1)   — aggregate 29 feats, then GEMM
    k_agg<29, false, X_, A_><<<gW, TB>>>(x, nullptr, nullptr);
    k_gemm<29, 96, true, true, A_, B_>
        <<<ceil_div(NN, (256/96)*4), (256/96)*96>>>(nullptr, W1, b1, nullptr);

    // layer 2: h2 = (A h1) W2 + b2       — aggregate 96 feats, then GEMM
    k_agg<96, false, B_, A_><<<gW, TB>>>(nullptr, nullptr, nullptr);
    k_gemm<96, 128, true, false, A_, B_>
        <<<ceil_div(NN, (256/128)*4), 256>>>(nullptr, W2, b2, nullptr);

    // layer 3: h3 = A (h2 W3) + b3       — GEMM first (64 < 128), agg with bias
    k_gemm<128, 64, false, false, B_, A_>
        <<<ceil_div(NN, (256/64)*4), 256>>>(nullptr, W3, nullptr, nullptr);
    k_agg<64, true, A_, B_><<<gW, TB>>>(nullptr, b3, nullptr);

    // layer 4: out = A (h3 W4) + b4      — GEMM first (32 < 64), agg with bias
    k_gemm<64, 32, false, false, B_, A_>
        <<<ceil_div(NN, (256/32)*4), 256>>>(nullptr, W4, nullptr, nullptr);
    k_agg<32, true, A_, X_><<<gW, TB>>>(nullptr, b4, out);

    (void)in_sizes; (void)n_in; (void)out_size;
}

// round 7
// speedup vs baseline: 1.4681x; 1.0049x over previous
#include <cuda_runtime.h>

#define NN 50000
#define EE 800000
#define ET 850000   // EE + NN self-loops
#define SB 512      // scan block size
#define NB ((NN + SB - 1) / SB)   // 98 scan blocks

// ---------------- scratch (device globals; no runtime allocation) ----------
__device__ int   g_deg[NN];
__device__ int   g_cur[NN];
__device__ int   g_off[NN + 1];
__device__ float g_dis[NN];
__device__ int   g_rowE[EE];
__device__ int   g_colE[EE];
__device__ int   g_part[NB];
__device__ int   g_pscan[NB];
__device__ int   g_src[ET];
__device__ float g_w[ET];
__device__ float g_bufA[(size_t)NN * 128];
__device__ float g_bufB[(size_t)NN * 128];

// Compile-time buffer selector (no host-side symbol lookup).
enum Which { A_, B_, X_ };
template <Which W>
__device__ __forceinline__ const float* inbuf(const float* ext) {
    if constexpr (W == A_) return g_bufA;
    else if constexpr (W == B_) return g_bufB;
    else return ext;
}
template <Which W>
__device__ __forceinline__ float* outbuf(float* ext) {
    if constexpr (W == A_) return g_bufA;
    else if constexpr (W == B_) return g_bufB;
    else return ext;
}

// ---------------- graph prep ------------------------------------------------
__global__ void k_zero() {
    int i = blockIdx.x * blockDim.x + threadIdx.x;
    if (i < NN) { g_deg[i] = 0; g_cur[i] = 0; }
}

// edge_index is int32 (JAX x64 disabled)
__global__ void k_count(const int* __restrict__ ei) {
    int e = blockIdx.x * blockDim.x + threadIdx.x;
    if (e >= EE) return;
    int r = ei[e];
    int c = ei[EE + e];
    if ((unsigned)r >= NN) r = 0;   // never trap on bad data (no-op when valid)
    if ((unsigned)c >= NN) c = 0;
    g_rowE[e] = r;
    g_colE[e] = c;
    atomicAdd(&g_deg[c], 1);
}

// phase 1: per-block sums of (deg[i]+1)
__global__ __launch_bounds__(SB) void k_scan1() {
    __shared__ int s[SB];
    int t = threadIdx.x;
    int i = blockIdx.x * SB + t;
    s[t] = (i < NN) ? (g_deg[i] + 1) : 0;
    __syncthreads();
#pragma unroll
    for (int o = SB / 2; o > 0; o >>= 1) {
        if (t < o) s[t] += s[t + o];
        __syncthreads();
    }
    if (t == 0) g_part[blockIdx.x] = s[0];
}

// phase 2: exclusive scan of the NB partials (single block of 128)
__global__ __launch_bounds__(128) void k_scan2() {
    __shared__ int s[128];
    int t = threadIdx.x;
    int v = (t < NB) ? g_part[t] : 0;
    s[t] = v;
    __syncthreads();
#pragma unroll
    for (int o = 1; o < 128; o <<= 1) {
        int u = (t >= o) ? s[t - o] : 0;
        __syncthreads();
        s[t] += u;
        __syncthreads();
    }
    if (t < NB) g_pscan[t] = s[t] - v;
    if (t == 0) g_off[NN] = ET;   // total is a compile-time constant
}

// phase 3: block-local exclusive scan + base, write g_off and g_dis
__global__ __launch_bounds__(SB) void k_scan3() {
    __shared__ int s[SB];
    int t = threadIdx.x;
    int i = blockIdx.x * SB + t;
    int d = (i < NN) ? g_deg[i] : 0;
    int v = (i < NN) ? (d + 1) : 0;
    s[t] = v;
    __syncthreads();
#pragma unroll
    for (int o = 1; o < SB; o <<= 1) {
        int u = (t >= o) ? s[t - o] : 0;
        __syncthreads();
        s[t] += u;
        __syncthreads();
    }
    if (i < NN) {
        g_off[i] = g_pscan[blockIdx.x] + s[t] - v;
        g_dis[i] = rsqrtf((float)(d + 1));
    }
}

// fill CSR: edges + self loops in one kernel
__global__ void k_fillself() {
    int e = blockIdx.x * blockDim.x + threadIdx.x;
    if (e < EE) {
        int r = g_rowE[e], c = g_colE[e];
        int p = atomicAdd(&g_cur[c], 1);
        int idx = g_off[c] + p;
        g_src[idx] = r;
        g_w[idx] = g_dis[r] * g_dis[c];
    } else if (e < EE + NN) {
        int n = e - EE;
        int idx = g_off[n + 1] - 1;   // last slot of each segment
        g_src[idx] = n;
        float d = g_dis[n];
        g_w[idx] = d * d;
    }
}

// ---------------- scalar aggregation (F not divisible by 4: F=29) ----------
template <int F, bool BIAS, Which SRC, Which DST>
__global__ __launch_bounds__(256) void k_agg(const float* __restrict__ ext_in,
                                             const float* __restrict__ b,
                                             float* __restrict__ ext_out) {
    const float* __restrict__ h = inbuf<SRC>(ext_in);
    float* __restrict__ out = outbuf<DST>(ext_out);
    constexpr int NACC = (F + 31) / 32;
    int warp = (blockIdx.x * blockDim.x + threadIdx.x) >> 5;
    int lane = threadIdx.x & 31;
    if (warp >= NN) return;
    int n = warp;
    int s = g_off[n], e = g_off[n + 1];
    float acc[NACC];
#pragma unroll
    for (int j = 0; j < NACC; j++) acc[j] = 0.f;
    for (int i = s; i < e; i++) {
        int src = g_src[i];
        float w = g_w[i];
        const float* hp = h + (size_t)src * F;
#pragma unroll
        for (int j = 0; j < NACC; j++) {
            int f = lane + 32 * j;
            if (f < F) acc[j] += w * __ldg(hp + f);
        }
    }
    float* op = out + (size_t)n * F;
#pragma unroll
    for (int j = 0; j < NACC; j++) {
        int f = lane + 32 * j;
        if (f < F) op[f] = acc[j] + (BIAS ? b[f] : 0.f);
    }
}

// ---------------- vectorized aggregation (F % 4 == 0) -----------------------
// L = F/4 lanes per edge, G = 32/L edge-groups per warp (F=96: L=24, G=1;
// F=64: L=16, G=2; F=32: L=8, G=4). Each group walks an independent strided
// slice of the edge list (shorter chains, more MLP); accumulators combined
// once at the end with log2(G) shfl_xor (NOT per-edge).
template <int F, bool BIAS, Which SRC, Which DST>
__global__ __launch_bounds__(256) void k_agg4(const float* __restrict__ ext_in,
                                              const float* __restrict__ b,
                                              float* __restrict__ ext_out) {
    static_assert(F % 4 == 0, "F must be divisible by 4");
    constexpr int L = F / 4;     // lanes per edge
    constexpr int G = 32 / L;    // concurrent edges per warp
    const float* __restrict__ h = inbuf<SRC>(ext_in);
    float* __restrict__ out = outbuf<DST>(ext_out);
    int warp = (blockIdx.x * blockDim.x + threadIdx.x) >> 5;
    int lane = threadIdx.x & 31;
    if (warp >= NN) return;
    int g = lane / L;
    int q = lane - g * L;
    int s = g_off[warp], e = g_off[warp + 1];
    float4 acc = make_float4(0.f, 0.f, 0.f, 0.f);
    if (g < G) {
        for (int i = s + g; i < e; i += G) {
            int   src = g_src[i];
            float w   = g_w[i];
            float4 v = __ldg((const float4*)(h + (size_t)src * F) + q);
            acc.x += w * v.x; acc.y += w * v.y;
            acc.z += w * v.z; acc.w += w * v.w;
        }
    }
    // combine group accumulators (no-op when G == 1)
#pragma unroll
    for (int st = G / 2; st >= 1; st >>= 1) {
        int off = st * L;
        acc.x += __shfl_xor_sync(0xffffffffu, acc.x, off);
        acc.y += __shfl_xor_sync(0xffffffffu, acc.y, off);
        acc.z += __shfl_xor_sync(0xffffffffu, acc.z, off);
        acc.w += __shfl_xor_sync(0xffffffffu, acc.w, off);
    }
    if (g == 0) {
        if (BIAS) {
            float4 bb = __ldg((const float4*)b + q);
            acc.x += bb.x; acc.y += bb.y; acc.z += bb.z; acc.w += bb.w;
        }
        ((float4*)(out + (size_t)warp * F))[q] = acc;
    }
}

// ---------------- GEMM: out[n][o] = (bias[o]) + sum_k x[n][k]*W[k][o] ------
template <int IN, int OUT, bool BIAS, bool RELU, Which SRC, Which DST>
__global__ void k_gemm(const float* __restrict__ ext_in,
                       const float* __restrict__ W,
                       const float* __restrict__ b,
                       float* __restrict__ ext_out) {
    const float* __restrict__ x = inbuf<SRC>(ext_in);
    float* __restrict__ out = outbuf<DST>(ext_out);
    constexpr int YB = 256 / OUT;       // 96->2,128->2,64->4,32->8
    constexpr int NPT = 4;              // nodes per thread (known-good)
    __shared__ float Ws[IN * OUT];
    for (int i = threadIdx.x; i < IN * OUT; i += blockDim.x) Ws[i] = W[i];
    __syncthreads();
    int o = threadIdx.x % OUT;
    int yy = threadIdx.x / OUT;
    int nodeBase = (blockIdx.x * YB + yy) * NPT;
    if (nodeBase >= NN) return;
    float acc[NPT];
    float bias = BIAS ? b[o] : 0.f;
#pragma unroll
    for (int j = 0; j < NPT; j++) acc[j] = 0.f;
    const float* xr = x + (size_t)nodeBase * IN;
    if (nodeBase + NPT <= NN) {
#pragma unroll
        for (int k = 0; k < IN; k++) {
            float w = Ws[k * OUT + o];
#pragma unroll
            for (int j = 0; j < NPT; j++) acc[j] += xr[(size_t)j * IN + k] * w;
        }
#pragma unroll
        for (int j = 0; j < NPT; j++) {
            float v = acc[j] + bias;
            out[(size_t)(nodeBase + j) * OUT + o] = RELU ? fmaxf(v, 0.f) : v;
        }
    } else {
        for (int k = 0; k < IN; k++) {
            float w = Ws[k * OUT + o];
#pragma unroll
            for (int j = 0; j < NPT; j++)
                if (nodeBase + j < NN) acc[j] += xr[(size_t)j * IN + k] * w;
        }
#pragma unroll
        for (int j = 0; j < NPT; j++)
            if (nodeBase + j < NN) {
                float v = acc[j] + bias;
                out[(size_t)(nodeBase + j) * OUT + o] = RELU ? fmaxf(v, 0.f) : v;
            }
    }
}

// ---------------- launch ----------------------------------------------------
static inline int ceil_div(int a, int b) { return (a + b - 1) / b; }

extern "C" void kernel_launch(void* const* d_in, const int* in_sizes, int n_in,
                              void* d_out, int out_size) {
    const float* x  = (const float*)d_in[0];
    const int*   ei = (const int*)d_in[1];   // int32 edge_index (2, E)
    const float* W1 = (const float*)d_in[2]; const float* b1 = (const float*)d_in[3];
    const float* W2 = (const float*)d_in[4]; const float* b2 = (const float*)d_in[5];
    const float* W3 = (const float*)d_in[6]; const float* b3 = (const float*)d_in[7];
    const float* W4 = (const float*)d_in[8]; const float* b4 = (const float*)d_in[9];
    float* out = (float*)d_out;

    const int TB = 256;
    const int gN  = ceil_div(NN, TB);
    const int gE  = ceil_div(EE, TB);
    const int gET = ceil_div(ET, TB);
    const int gW  = ceil_div(NN, TB / 32);   // one warp per node

    // graph prep
    k_zero<<<gN, TB>>>();
    k_count<<<gE, TB>>>(ei);
    k_scan1<<<NB, SB>>>();
    k_scan2<<<1, 128>>>();
    k_scan3<<<NB, SB>>>();
    k_fillself<<<gET, TB>>>();

    // layer 1: h1 = relu((A x) W1 + b1)   — aggregate 29 feats, then GEMM
    k_agg<29, false, X_, A_><<<gW, TB>>>(x, nullptr, nullptr);
    k_gemm<29, 96, true, true, A_, B_>
        <<<ceil_div(NN, (256/96)*4), (256/96)*96>>>(nullptr, W1, b1, nullptr);

    // layer 2: h2 = (A h1) W2 + b2       — aggregate 96 feats, then GEMM
    k_agg4<96, false, B_, A_><<<gW, TB>>>(nullptr, nullptr, nullptr);
    k_gemm<96, 128, true, false, A_, B_>
        <<<ceil_div(NN, (256/128)*4), 256>>>(nullptr, W2, b2, nullptr);

    // layer 3: h3 = A (h2 W3) + b3       — GEMM first (64 < 128), agg with bias
    k_gemm<128, 64, false, false, B_, A_>
        <<<ceil_div(NN, (256/64)*4), 256>>>(nullptr, W3, nullptr, nullptr);
    k_agg4<64, true, A_, B_><<<gW, TB>>>(nullptr, b3, nullptr);

    // layer 4: out = A (h3 W4) + b4      — GEMM first (32 < 64), agg with bias
    k_gemm<64, 32, false, false, B_, A_>
        <<<ceil_div(NN, (256/32)*4), 256>>>(nullptr, W4, nullptr, nullptr);
    k_agg4<32, true, A_, X_><<<gW, TB>>>(nullptr, b4, out);

    (void)in_sizes; (void)n_in; (void)out_size;
}

// round 9
// speedup vs baseline: 2.3396x; 1.5937x over previous
#include <cuda_runtime.h>

#define NN 50000
#define EE 800000
#define ET 850000   // EE + NN self-loops
#define SB 512      // scan block size
#define NB ((NN + SB - 1) / SB)   // 98 scan blocks

// ---------------- scratch (device globals; no runtime allocation) ----------
__device__ int   g_deg[NN];
__device__ int   g_cur[NN];
__device__ int   g_off[NN + 1];
__device__ float g_dis[NN];
__device__ int   g_rowE[EE];
__device__ int   g_colE[EE];
__device__ int   g_part[NB];
__device__ int   g_pscan[NB];
__device__ int   g_src[ET];
__device__ float g_w[ET];
__device__ float g_bufA[(size_t)NN * 128];
__device__ float g_bufB[(size_t)NN * 128];

// Compile-time buffer selector (no host-side symbol lookup).
enum Which { A_, B_, X_ };
template <Which W>
__device__ __forceinline__ const float* inbuf(const float* ext) {
    if constexpr (W == A_) return g_bufA;
    else if constexpr (W == B_) return g_bufB;
    else return ext;
}
template <Which W>
__device__ __forceinline__ float* outbuf(float* ext) {
    if constexpr (W == A_) return g_bufA;
    else if constexpr (W == B_) return g_bufB;
    else return ext;
}

// ---------------- graph prep ------------------------------------------------
__global__ void k_zero() {
    int i = blockIdx.x * blockDim.x + threadIdx.x;
    if (i < NN) { g_deg[i] = 0; g_cur[i] = 0; }
}

// edge_index is int32 (JAX x64 disabled)
__global__ void k_count(const int* __restrict__ ei) {
    int e = blockIdx.x * blockDim.x + threadIdx.x;
    if (e >= EE) return;
    int r = ei[e];
    int c = ei[EE + e];
    if ((unsigned)r >= NN) r = 0;   // never trap on bad data (no-op when valid)
    if ((unsigned)c >= NN) c = 0;
    g_rowE[e] = r;
    g_colE[e] = c;
    atomicAdd(&g_deg[c], 1);
}

// phase 1: per-block sums of (deg[i]+1)
__global__ __launch_bounds__(SB) void k_scan1() {
    __shared__ int s[SB];
    int t = threadIdx.x;
    int i = blockIdx.x * SB + t;
    s[t] = (i < NN) ? (g_deg[i] + 1) : 0;
    __syncthreads();
#pragma unroll
    for (int o = SB / 2; o > 0; o >>= 1) {
        if (t < o) s[t] += s[t + o];
        __syncthreads();
    }
    if (t == 0) g_part[blockIdx.x] = s[0];
}

// phase 2: exclusive scan of the NB partials (single block of 128)
__global__ __launch_bounds__(128) void k_scan2() {
    __shared__ int s[128];
    int t = threadIdx.x;
    int v = (t < NB) ? g_part[t] : 0;
    s[t] = v;
    __syncthreads();
#pragma unroll
    for (int o = 1; o < 128; o <<= 1) {
        int u = (t >= o) ? s[t - o] : 0;
        __syncthreads();
        s[t] += u;
        __syncthreads();
    }
    if (t < NB) g_pscan[t] = s[t] - v;
    if (t == 0) g_off[NN] = ET;   // total is a compile-time constant
}

// phase 3: block-local exclusive scan + base, write g_off and g_dis
__global__ __launch_bounds__(SB) void k_scan3() {
    __shared__ int s[SB];
    int t = threadIdx.x;
    int i = blockIdx.x * SB + t;
    int d = (i < NN) ? g_deg[i] : 0;
    int v = (i < NN) ? (d + 1) : 0;
    s[t] = v;
    __syncthreads();
#pragma unroll
    for (int o = 1; o < SB; o <<= 1) {
        int u = (t >= o) ? s[t - o] : 0;
        __syncthreads();
        s[t] += u;
        __syncthreads();
    }
    if (i < NN) {
        g_off[i] = g_pscan[blockIdx.x] + s[t] - v;
        g_dis[i] = rsqrtf((float)(d + 1));
    }
}

// fill CSR: edges + self loops in one kernel
__global__ void k_fillself() {
    int e = blockIdx.x * blockDim.x + threadIdx.x;
    if (e < EE) {
        int r = g_rowE[e], c = g_colE[e];
        int p = atomicAdd(&g_cur[c], 1);
        int idx = g_off[c] + p;
        g_src[idx] = r;
        g_w[idx] = g_dis[r] * g_dis[c];
    } else if (e < EE + NN) {
        int n = e - EE;
        int idx = g_off[n + 1] - 1;   // last slot of each segment
        g_src[idx] = n;
        float d = g_dis[n];
        g_w[idx] = d * d;
    }
}

// ---------------- scalar aggregation (F not divisible by 4: F=29) ----------
template <int F, bool BIAS, Which SRC, Which DST>
__global__ __launch_bounds__(256) void k_agg(const float* __restrict__ ext_in,
                                             const float* __restrict__ b,
                                             float* __restrict__ ext_out) {
    const float* __restrict__ h = inbuf<SRC>(ext_in);
    float* __restrict__ out = outbuf<DST>(ext_out);
    constexpr int NACC = (F + 31) / 32;
    int warp = (blockIdx.x * blockDim.x + threadIdx.x) >> 5;
    int lane = threadIdx.x & 31;
    if (warp >= NN) return;
    int n = warp;
    int s = g_off[n], e = g_off[n + 1];
    float acc[NACC];
#pragma unroll
    for (int j = 0; j < NACC; j++) acc[j] = 0.f;
    for (int i = s; i < e; i++) {
        int src = g_src[i];
        float w = g_w[i];
        const float* hp = h + (size_t)src * F;
#pragma unroll
        for (int j = 0; j < NACC; j++) {
            int f = lane + 32 * j;
            if (f < F) acc[j] += w * __ldg(hp + f);
        }
    }
    float* op = out + (size_t)n * F;
#pragma unroll
    for (int j = 0; j < NACC; j++) {
        int f = lane + 32 * j;
        if (f < F) op[f] = acc[j] + (BIAS ? b[f] : 0.f);
    }
}

// ---------------- vectorized aggregation (F % 4 == 0) -----------------------
template <int F, bool BIAS, Which SRC, Which DST>
__global__ __launch_bounds__(256) void k_agg4(const float* __restrict__ ext_in,
                                              const float* __restrict__ b,
                                              float* __restrict__ ext_out) {
    static_assert(F % 4 == 0, "F must be divisible by 4");
    constexpr int L = F / 4;     // lanes per edge
    constexpr int G = 32 / L;    // concurrent edges per warp
    const float* __restrict__ h = inbuf<SRC>(ext_in);
    float* __restrict__ out = outbuf<DST>(ext_out);
    int warp = (blockIdx.x * blockDim.x + threadIdx.x) >> 5;
    int lane = threadIdx.x & 31;
    if (warp >= NN) return;
    int g = lane / L;
    int q = lane - g * L;
    int s = g_off[warp], e = g_off[warp + 1];
    float4 acc = make_float4(0.f, 0.f, 0.f, 0.f);
    if (g < G) {
        for (int i = s + g; i < e; i += G) {
            int   src = g_src[i];
            float w   = g_w[i];
            float4 v = __ldg((const float4*)(h + (size_t)src * F) + q);
            acc.x += w * v.x; acc.y += w * v.y;
            acc.z += w * v.z; acc.w += w * v.w;
        }
    }
#pragma unroll
    for (int st = G / 2; st >= 1; st >>= 1) {
        int off = st * L;
        acc.x += __shfl_xor_sync(0xffffffffu, acc.x, off);
        acc.y += __shfl_xor_sync(0xffffffffu, acc.y, off);
        acc.z += __shfl_xor_sync(0xffffffffu, acc.z, off);
        acc.w += __shfl_xor_sync(0xffffffffu, acc.w, off);
    }
    if (g == 0) {
        if (BIAS) {
            float4 bb = __ldg((const float4*)b + q);
            acc.x += bb.x; acc.y += bb.y; acc.z += bb.z; acc.w += bb.w;
        }
        ((float4*)(out + (size_t)warp * F))[q] = acc;
    }
}

// ---------------- tiled GEMM: out[n][o] = bias + sum_k x[n][k]*W[k][o] ------
// 64-node x TN-output tile per 256-thread block. W slice loaded ONCE per
// block (782 node-blocks, not 6250 -> ~95% less weight traffic). Each
// thread computes a 4xVN register tile; inner loop is 2 LDS + 4*VN FFMA.
template <int IN, int OUT, int NOB, bool BIAS, bool RELU, Which SRC, Which DST>
__global__ __launch_bounds__(256) void k_gemm_t(const float* __restrict__ ext_in,
                                                const float* __restrict__ W,
                                                const float* __restrict__ b,
                                                float* __restrict__ ext_out) {
    constexpr int TN  = OUT / NOB;                 // 48, 64, 64, 32
    constexpr int VN  = TN / 16;                   // 3, 4, 4, 2
    constexpr int KT  = 16;
    constexpr int INP = ((IN + KT - 1) / KT) * KT; // 32, 96, 128, 64
    const float* __restrict__ x = inbuf<SRC>(ext_in);
    float* __restrict__ out = outbuf<DST>(ext_out);

    __shared__ float Xs[KT][64];
    __shared__ float Wsm[INP][TN];

    int t  = threadIdx.x;
    int tx = t & 15, ty = t >> 4;
    int mB = blockIdx.x * 64;
    int oB = blockIdx.y * TN;

    // load W slice into shared (zero-pad k >= IN)
    for (int i = t; i < INP * TN; i += 256) {
        int k = i / TN, o = i % TN;
        Wsm[k][o] = (k < IN) ? W[k * OUT + oB + o] : 0.f;
    }

    float acc[4][VN];
#pragma unroll
    for (int i = 0; i < 4; i++)
#pragma unroll
        for (int j = 0; j < VN; j++) acc[i][j] = 0.f;

    int mLoad = t >> 2;            // 0..63: node this thread stages
    int c4    = (t & 3) * 4;       // k-offset within tile
    const float* xrow = x + (size_t)(mB + mLoad) * IN;
    bool mvalid = (mB + mLoad) < NN;

    for (int kb = 0; kb < INP; kb += KT) {
        float4 v = make_float4(0.f, 0.f, 0.f, 0.f);
        if (mvalid) {
            int k0 = kb + c4;
            if constexpr (IN % 4 == 0) {
                v = *(const float4*)(xrow + k0);   // rows 16B-aligned
            } else {
                if (k0 + 0 < IN) v.x = xrow[k0 + 0];
                if (k0 + 1 < IN) v.y = xrow[k0 + 1];
                if (k0 + 2 < IN) v.z = xrow[k0 + 2];
                if (k0 + 3 < IN) v.w = xrow[k0 + 3];
            }
        }
        __syncthreads();           // previous tile fully consumed (also orders Wsm)
        Xs[c4 + 0][mLoad] = v.x;
        Xs[c4 + 1][mLoad] = v.y;
        Xs[c4 + 2][mLoad] = v.z;
        Xs[c4 + 3][mLoad] = v.w;
        __syncthreads();
#pragma unroll
        for (int kk = 0; kk < KT; kk++) {
            float4 xv = *(const float4*)&Xs[kk][ty * 4];
            float wv[VN];
#pragma unroll
            for (int j = 0; j < VN; j++) wv[j] = Wsm[kb + kk][tx * VN + j];
#pragma unroll
            for (int j = 0; j < VN; j++) {
                acc[0][j] += xv.x * wv[j];
                acc[1][j] += xv.y * wv[j];
                acc[2][j] += xv.z * wv[j];
                acc[3][j] += xv.w * wv[j];
            }
        }
    }

#pragma unroll
    for (int i = 0; i < 4; i++) {
        int m = mB + ty * 4 + i;
        if (m < NN) {
#pragma unroll
            for (int j = 0; j < VN; j++) {
                int o = oB + tx * VN + j;
                float vv = acc[i][j] + (BIAS ? __ldg(b + o) : 0.f);
                out[(size_t)m * OUT + o] = RELU ? fmaxf(vv, 0.f) : vv;
            }
        }
    }
}

// ---------------- launch ----------------------------------------------------
static inline int ceil_div(int a, int b) { return (a + b - 1) / b; }

extern "C" void kernel_launch(void* const* d_in, const int* in_sizes, int n_in,
                              void* d_out, int out_size) {
    const float* x  = (const float*)d_in[0];
    const int*   ei = (const int*)d_in[1];   // int32 edge_index (2, E)
    const float* W1 = (const float*)d_in[2]; const float* b1 = (const float*)d_in[3];
    const float* W2 = (const float*)d_in[4]; const float* b2 = (const float*)d_in[5];
    const float* W3 = (const float*)d_in[6]; const float* b3 = (const float*)d_in[7];
    const float* W4 = (const float*)d_in[8]; const float* b4 = (const float*)d_in[9];
    float* out = (float*)d_out;

    const int TB = 256;
    const int gN  = ceil_div(NN, TB);
    const int gE  = ceil_div(EE, TB);
    const int gET = ceil_div(ET, TB);
    const int gW  = ceil_div(NN, TB / 32);   // one warp per node
    const int gM  = ceil_div(NN, 64);        // gemm node-blocks (782)

    // graph prep
    k_zero<<<gN, TB>>>();
    k_count<<<gE, TB>>>(ei);
    k_scan1<<<NB, SB>>>();
    k_scan2<<<1, 128>>>();
    k_scan3<<<NB, SB>>>();
    k_fillself<<<gET, TB>>>();

    // layer 1: h1 = relu((A x) W1 + b1)   — aggregate 29 feats, then GEMM
    k_agg<29, false, X_, A_><<<gW, TB>>>(x, nullptr, nullptr);
    k_gemm_t<29, 96, 2, true, true, A_, B_><<<dim3(gM, 2), TB>>>(nullptr, W1, b1, nullptr);

    // layer 2: h2 = (A h1) W2 + b2       — aggregate 96 feats, then GEMM
    k_agg4<96, false, B_, A_><<<gW, TB>>>(nullptr, nullptr, nullptr);
    k_gemm_t<96, 128, 2, true, false, A_, B_><<<dim3(gM, 2), TB>>>(nullptr, W2, b2, nullptr);

    // layer 3: h3 = A (h2 W3) + b3       — GEMM first (64 < 128), agg with bias
    k_gemm_t<128, 64, 1, false, false, B_, A_><<<dim3(gM, 1), TB>>>(nullptr, W3, nullptr, nullptr);
    k_agg4<64, true, A_, B_><<<gW, TB>>>(nullptr, b3, nullptr);

    // layer 4: out = A (h3 W4) + b4      — GEMM first (32 < 64), agg with bias
    k_gemm_t<64, 32, 1, false, false, B_, A_><<<dim3(gM, 1), TB>>>(nullptr, W4, nullptr, nullptr);
    k_agg4<32, true, A_, X_><<<gW, TB>>>(nullptr, b4, out);

    (void)in_sizes; (void)n_in; (void)out_size;
}